// round 11
// baseline (speedup 1.0000x reference)
#include <cuda_runtime.h>
#include <cuda_bf16.h>
#include <math.h>

// ---------------- problem constants ----------------
#define NB      16
#define CDIM    256
#define HID     64
#define HDIM    128
#define WDIM    128
#define NTOK    (HDIM*WDIM)     // 16384
#define NPAT    256
#define NKEEP   179
#define NKH     12
#define NKW     16
#define NPOUT   (NKH*NKW)       // 192
#define OUT_TOK (NKH*8*NKW*8)   // 12288
#define C4      (CDIM/4)

#define WINDOW  0.012f          // validated in rounds 6/8; 0.0025 flips (round 9)

typedef unsigned int uint;
typedef unsigned long long ull;

// ---------------- scorer smem map (32-bit words / bytes) ----------------
// A fragment buffer: 128 rows x 36 words (pad 36 -> STS.128-aligned) = 18432 B
#define A_PAD    36
#define A_WORDS  (128 * A_PAD)          // 4608 words per buffer
#define SM_A     0
#define SM_TOK   36864                  // after 2 A buffers (bytes)
#define SM_B1    37376
#define SM_W2    37632
#define SMEM_BYTES 37888

// ---------------- device scratch ----------------
__device__ uint  g_Wf[8192];                  // W1 bf16 hi fragment image
__device__ float g_rowpart[NB * HDIM * 16];   // per-image-row patch partials
__device__ int   g_kept[NB * NPOUT];
__device__ int   g_keepC[NB * NPAT];          // certain-keep flags
__device__ int   g_amb[NB * NPAT];            // ambiguous patch ids
__device__ float g_exc[NB * NPAT];            // exact scores of ambiguous
__device__ int   g_nA[NB], g_nC[NB];

// ---------------- helpers ----------------
static __device__ __forceinline__ uint cvt_bf2(float hi, float lo) {
    uint d;
    asm("cvt.rn.bf16x2.f32 %0, %1, %2;" : "=r"(d) : "f"(hi), "f"(lo));
    return d;
}
static __device__ __forceinline__ void mma16816(float* d, const uint* a,
                                                uint b0, uint b1) {
    asm("mma.sync.aligned.m16n8k16.row.col.f32.bf16.bf16.f32 "
        "{%0,%1,%2,%3}, {%4,%5,%6,%7}, {%8,%9}, {%0,%1,%2,%3};"
        : "+f"(d[0]), "+f"(d[1]), "+f"(d[2]), "+f"(d[3])
        : "r"(a[0]), "r"(a[1]), "r"(a[2]), "r"(a[3]), "r"(b0), "r"(b1));
}
static __device__ __forceinline__ void ffma2(ull& d, ull a, ull b) {
    asm("fma.rn.f32x2 %0, %1, %2, %0;" : "+l"(d) : "l"(a), "l"(b));
}
static __device__ __forceinline__ ull pack2(float v) {
    ull r;
    asm("mov.b64 %0, {%1, %1};" : "=l"(r) : "f"(v));
    return r;
}

// =====================================================================
// prep: W1 [256k x 64n] fp32 -> bf16 (hi) in m16n8k16 B-fragment order.
// =====================================================================
__global__ __launch_bounds__(256) void prep_W_kernel(const float* __restrict__ W1) {
    int u = blockIdx.x * 256 + threadIdx.x;     // 0..8191
    int reg = u & 1, lane = (u >> 1) & 31, ns = (u >> 6) & 7, ks = u >> 9;
    int g = lane >> 2, t = lane & 3;
    int k0 = ks * 16 + 2 * t + 8 * reg;
    int n  = ns * 8 + g;
    g_Wf[u] = cvt_bf2(W1[(k0 + 1) * HID + n], W1[k0 * HID + n]);
}

// =====================================================================
// approx scorer: one block = 128 tokens (1 image row). single-product
// bf16 HMMA GEMM (M=128, N=64, K=256) + fused epilogue.
// Double-buffered A staging (1 barrier/chunk) + STS.128 fragment stores.
// =====================================================================
__global__ __launch_bounds__(128, 4) void scorer_kernel(
    const float* __restrict__ tokens,
    const float* __restrict__ b1g,
    const float* __restrict__ W2g,
    const float* __restrict__ b2g)
{
    extern __shared__ char smem[];
    uint*  sA0  = (uint*)(smem + SM_A);
    float* sTok = (float*)(smem + SM_TOK);
    float* sb1  = (float*)(smem + SM_B1);
    float* sw2  = (float*)(smem + SM_W2);

    const int tid  = threadIdx.x;
    const int w    = tid >> 5;
    const int lane = tid & 31;
    const int blk  = blockIdx.x;

    if (tid < 64) { sb1[tid] = b1g[tid]; sw2[tid] = W2g[tid]; }

    float acc[2][8][4];
    #pragma unroll
    for (int a = 0; a < 2; a++)
        #pragma unroll
        for (int b = 0; b < 8; b++)
            #pragma unroll
            for (int c = 0; c < 4; c++) acc[a][b][c] = 0.f;

    const int m = tid;
    const int mstep = m >> 4, r = m & 15, q = r & 7, rh = r >> 3;
    const float4* rowp = (const float4*)(tokens + ((size_t)blk * 128 + m) * CDIM);
    const uint2* gWh = (const uint2*)g_Wf;

    for (int c = 0; c < 4; ++c) {               // 4 chunks of 64 channels
        uint* buf = sA0 + (c & 1) * A_WORDS;
        // ---- convert 64 channels into A-fragment layout ----
        #pragma unroll
        for (int jj = 0; jj < 8; ++jj) {
            float4 a = rowp[c * 16 + 2 * jj];
            float4 b = rowp[c * 16 + 2 * jj + 1];
            uint h0 = cvt_bf2(a.y, a.x);
            uint h1 = cvt_bf2(a.w, a.z);
            uint h2 = cvt_bf2(b.y, b.x);
            uint h3 = cvt_bf2(b.w, b.z);
            int kl = jj >> 1, kh = jj & 1;
            uint w0 = (uint)((((kl * 8 + mstep) * 4) + rh + 2 * kh) * A_PAD + 4 * q);
            *(uint4*)(buf + w0) = make_uint4(h0, h1, h2, h3);   // STS.128
        }
        __syncthreads();                        // writes visible to all warps

        // ---- MMA over this chunk's 4 ksteps ----
        #pragma unroll
        for (int kl = 0; kl < 4; ++kl) {
            uint Ah[2][4];
            #pragma unroll
            for (int dm = 0; dm < 2; ++dm) {
                int msel = 2 * w + dm;
                #pragma unroll
                for (int rg = 0; rg < 4; ++rg)
                    Ah[dm][rg] = buf[(uint)(((kl * 8 + msel) * 4 + rg) * A_PAD + lane)];
            }
            int ks = c * 4 + kl;
            #pragma unroll
            for (int ns = 0; ns < 8; ++ns) {
                uint2 bh = __ldg(&gWh[(uint)((ks * 8 + ns) * 32 + lane)]);
                mma16816(acc[0][ns], Ah[0], bh.x, bh.y);
                mma16816(acc[1][ns], Ah[1], bh.x, bh.y);
            }
        }
    }

    // epilogue: bias + relu + W2 dot, reduce k-lanes, sigmoid
    const int t4 = lane & 3, g = lane >> 2;
    const float b2v = b2g[0];
    float tv[4];
    #pragma unroll
    for (int dm = 0; dm < 2; ++dm)
        #pragma unroll
        for (int rh2 = 0; rh2 < 2; ++rh2) {
            float s = 0.f;
            #pragma unroll
            for (int ns = 0; ns < 8; ++ns)
                #pragma unroll
                for (int j = 0; j < 2; ++j) {
                    int n = ns * 8 + 2 * t4 + j;
                    float h = acc[dm][ns][2 * rh2 + j] + sb1[n];
                    s += fmaxf(h, 0.f) * sw2[n];
                }
            tv[dm * 2 + rh2] = s;
        }
    #pragma unroll
    for (int k = 0; k < 4; ++k) {
        tv[k] += __shfl_xor_sync(0xffffffffu, tv[k], 1);
        tv[k] += __shfl_xor_sync(0xffffffffu, tv[k], 2);
    }
    __syncthreads();                            // A-buffer reads done; sTok safe
    if (t4 == 0) {
        #pragma unroll
        for (int k = 0; k < 4; ++k) {
            int dm = k >> 1, rh2 = k & 1;
            int token = (2 * w + dm) * 16 + g + 8 * rh2;
            sTok[token] = 1.f / (1.f + expf(-(tv[k] + b2v)));
        }
    }
    __syncthreads();

    if (tid < 16) {
        float sum = 0.f;
        #pragma unroll
        for (int cc = 0; cc < 8; ++cc) sum += sTok[tid * 8 + cc];
        int bb = blk >> 7, y = blk & 127;
        g_rowpart[(bb * HDIM + y) * 16 + tid] = sum;
    }
}

// =====================================================================
// select1: per batch. Approx ranking, find cut, classify into
// certain-keep / ambiguous (|s - cut| <= WINDOW) / certain-drop.
// =====================================================================
__global__ __launch_bounds__(256) void select1_kernel() {
    __shared__ float s[NPAT];
    __shared__ float sCut;
    __shared__ int flagA[NPAT];
    const int b = blockIdx.x;
    const int tid = threadIdx.x;
    const int ih = tid >> 4, iw = tid & 15;
    float sc = 0.f;
    #pragma unroll
    for (int r = 0; r < 8; r++)
        sc += g_rowpart[(b * HDIM + ih * 8 + r) * 16 + iw];
    s[tid] = sc;
    __syncthreads();
    float my = s[tid];
    int rank = 0;
    #pragma unroll 8
    for (int q = 0; q < NPAT; q++) {
        float v = s[q];
        rank += (v > my) || (v == my && q < tid);
    }
    if (rank == NKEEP - 1) sCut = my;
    __syncthreads();
    float d = my - sCut;
    int isC = (d > WINDOW) ? 1 : 0;
    int isA = (fabsf(d) <= WINDOW) ? 1 : 0;
    flagA[tid] = isA;
    g_keepC[b * NPAT + tid] = isC;
    __syncthreads();
    if (isA) {
        int pos = 0;
        for (int q = 0; q < tid; q++) pos += flagA[q];
        g_amb[b * NPAT + pos] = tid;
    }
    if (tid == 0) {
        int nA = 0;
        for (int q = 0; q < NPAT; q++) nA += flagA[q];
        g_nA[b] = nA;
    }
    if (tid == 1) {
        int nC = 0;
        for (int q = 0; q < NPAT; q++)
            nC += (int)(s[q] - sCut > WINDOW);
        g_nC[b] = nC;
    }
}

// =====================================================================
// rescore: exact fp32 score via packed FFMA2 for each ambiguous patch.
// grid (32, NB); block 256 = 64 tokens x 4 hidden-groups of 16.
// FLOP-bound -> f32x2 halves the bound. Fixed order => deterministic.
// =====================================================================
__global__ __launch_bounds__(256) void rescore_kernel(
    const float* __restrict__ tokens,
    const float* __restrict__ W1,
    const float* __restrict__ b1,
    const float* __restrict__ W2,
    const float* __restrict__ b2)
{
    const int b = blockIdx.y;
    const int nA = g_nA[b];

    __shared__ float sp[64 * 4];
    __shared__ float st[64];

    const int tid = threadIdx.x;
    const int t = tid >> 2, hh = tid & 3;       // token 0..63, hidden group
    const int rr = t >> 3, cc = t & 7;
    const int hb = hh * 16;

    for (int j = blockIdx.x; j < nA; j += 32) {
        const int p = g_amb[b * NPAT + j];
        const int ih = p >> 4, iw = p & 15;
        const int tokIdx = b * NTOK + (ih * 8 + rr) * WDIM + iw * 8 + cc;
        const float4* x4 = (const float4*)(tokens + (size_t)tokIdx * CDIM);

        ull hacc[8];                            // 16 hidden as 8 f32 pairs
        const ull* b1p = (const ull*)(b1 + hb); // hb*4 is 64B-mult -> aligned
        #pragma unroll
        for (int i = 0; i < 8; i++) hacc[i] = b1p[i];

        for (int c4 = 0; c4 < 64; ++c4) {
            float4 xv = __ldg(&x4[c4]);
            #pragma unroll
            for (int rr4 = 0; rr4 < 4; ++rr4) {
                float xc = (rr4 == 0) ? xv.x : (rr4 == 1) ? xv.y
                         : (rr4 == 2) ? xv.z : xv.w;
                ull xp = pack2(xc);
                const ulonglong2* wp =
                    (const ulonglong2*)(W1 + (size_t)(c4 * 4 + rr4) * HID + hb);
                ulonglong2 wA = __ldg(&wp[0]);
                ulonglong2 wB = __ldg(&wp[1]);
                ulonglong2 wC = __ldg(&wp[2]);
                ulonglong2 wD = __ldg(&wp[3]);
                ffma2(hacc[0], xp, wA.x); ffma2(hacc[1], xp, wA.y);
                ffma2(hacc[2], xp, wB.x); ffma2(hacc[3], xp, wB.y);
                ffma2(hacc[4], xp, wC.x); ffma2(hacc[5], xp, wC.y);
                ffma2(hacc[6], xp, wD.x); ffma2(hacc[7], xp, wD.y);
            }
        }
        float z = 0.f;
        #pragma unroll
        for (int i = 0; i < 8; i++) {
            float lo = __uint_as_float((uint)hacc[i]);
            float hi = __uint_as_float((uint)(hacc[i] >> 32));
            z += fmaxf(lo, 0.f) * __ldg(&W2[hb + 2 * i])
               + fmaxf(hi, 0.f) * __ldg(&W2[hb + 2 * i + 1]);
        }
        sp[t * 4 + hh] = z;
        __syncthreads();
        if (tid < 64) {
            float zz = b2[0] + sp[tid * 4] + sp[tid * 4 + 1]
                     + sp[tid * 4 + 2] + sp[tid * 4 + 3];
            st[tid] = 1.f / (1.f + expf(-zz));
        }
        __syncthreads();
        if (tid == 0) {
            float sum = 0.f;
            for (int q = 0; q < 64; q++) sum += st[q];
            g_exc[b * NPAT + j] = sum * (1.f / 64.f);
        }
        __syncthreads();
    }
}

// =====================================================================
// select2: merge certain keeps + top-(NKEEP - nC) ambiguous by exact
// score (desc, index asc). Emit kept ids ascending, pad -1.
// =====================================================================
__global__ __launch_bounds__(256) void select2_kernel() {
    __shared__ int keepF[NPAT];
    __shared__ float e[NPAT];
    __shared__ int aid[NPAT];
    const int b = blockIdx.x;
    const int tid = threadIdx.x;
    const int nA = g_nA[b];
    const int slots = NKEEP - g_nC[b];
    keepF[tid] = g_keepC[b * NPAT + tid];
    if (tid < nA) {
        e[tid] = g_exc[b * NPAT + tid];
        aid[tid] = g_amb[b * NPAT + tid];
    }
    __syncthreads();
    if (tid < nA) {
        float my = e[tid];
        int rank = 0;
        for (int q = 0; q < nA; q++) {
            float v = e[q];
            rank += (v > my) || (v == my && q < tid);
        }
        if (rank < slots) keepF[aid[tid]] = 1;
    }
    __syncthreads();
    int kept = keepF[tid];
    if (kept) {
        int pos = 0;
        for (int q = 0; q < tid; q++) pos += keepF[q];
        g_kept[b * NPOUT + pos] = tid;
    }
    if (tid >= NKEEP && tid < NPOUT) g_kept[b * NPOUT + tid] = -1;
}

// =====================================================================
// gather: one block per output patch slot. Streaming stores (__stcs)
// keep token reads L2-friendlier.
// =====================================================================
__global__ __launch_bounds__(256) void gather_kernel(
    const float4* __restrict__ tokens, float4* __restrict__ out)
{
    const int bk = blockIdx.x;
    const int b  = bk / NPOUT;
    const int kp = bk % NPOUT;
    const int s  = g_kept[b * NPOUT + kp];
    const int kh = kp >> 4, kw = kp & 15;

    const float4* srcB = tokens + (size_t)b * (NTOK * C4);
    float4* dstB = out + (size_t)b * (OUT_TOK * C4);

    int sih = 0, siw = 0;
    if (s >= 0) { sih = s >> 4; siw = s & 15; }
    const float4 zero = make_float4(0.f, 0.f, 0.f, 0.f);

    #pragma unroll
    for (int i = 0; i < 16; i++) {
        int idx = i * 256 + threadIdx.x;
        int tp  = idx >> 6;
        int c4  = idx & 63;
        int ph = tp >> 3, pw = tp & 7;
        int dstTok = (kh * 8 + ph) * WDIM + kw * 8 + pw;
        float4 v = zero;
        if (s >= 0) {
            int srcTok = (sih * 8 + ph) * WDIM + siw * 8 + pw;
            v = __ldg(&srcB[srcTok * C4 + c4]);
        }
        __stcs(&dstB[dstTok * C4 + c4], v);
    }
}

// =====================================================================
extern "C" void kernel_launch(void* const* d_in, const int* in_sizes, int n_in,
                              void* d_out, int out_size)
{
    const float* tokens = (const float*)d_in[0];
    const float* W1 = (const float*)d_in[1];
    const float* b1 = (const float*)d_in[2];
    const float* W2 = (const float*)d_in[3];
    const float* b2 = (const float*)d_in[4];
    float* out = (float*)d_out;

    cudaFuncSetAttribute(scorer_kernel,
                         cudaFuncAttributeMaxDynamicSharedMemorySize, SMEM_BYTES);

    prep_W_kernel<<<32, 256>>>(W1);
    scorer_kernel<<<NB * HDIM, 128, SMEM_BYTES>>>(tokens, b1, W2, b2);
    select1_kernel<<<NB, 256>>>();
    rescore_kernel<<<dim3(32, NB), 256>>>(tokens, W1, b1, W2, b2);
    select2_kernel<<<NB, 256>>>();
    gather_kernel<<<NB * NPOUT, 256>>>((const float4*)tokens, (float4*)out);
}

// round 12
// speedup vs baseline: 1.2316x; 1.2316x over previous
#include <cuda_runtime.h>
#include <cuda_bf16.h>
#include <math.h>

// ---------------- problem constants ----------------
#define NB      16
#define CDIM    256
#define HID     64
#define HDIM    128
#define WDIM    128
#define NTOK    (HDIM*WDIM)     // 16384
#define NPAT    256
#define NKEEP   179
#define NKH     12
#define NKW     16
#define NPOUT   (NKH*NKW)       // 192
#define OUT_TOK (NKH*8*NKW*8)   // 12288
#define C4      (CDIM/4)

#define WINDOW  0.012f          // validated rounds 6/8; 0.0025 flips (round 9)
#define RSX     64              // rescore grid.x

typedef unsigned int uint;
typedef unsigned long long ull;

// ---------------- scorer smem map ----------------
#define A_PAD    36
#define A_WORDS  (128 * A_PAD)          // 4608 words per buffer
#define SM_A     0
#define SM_TOK   36864                  // after 2 A buffers (bytes)
#define SM_B1    37376
#define SM_W2    37632
#define SMEM_BYTES 37888

// rescore dynamic smem: W1 (16384 f) + X (16384 f) + sp (256 f) + st (64 f)
#define RS_SMEM_BYTES ((16384 + 16384 + 256 + 64) * 4)

// ---------------- device scratch ----------------
__device__ uint  g_Wf[8192];                  // W1 bf16 hi fragment image
__device__ float g_rowpart[NB * HDIM * 16];   // per-image-row patch partials
__device__ int   g_kept[NB * NPOUT];
__device__ int   g_keepC[NB * NPAT];          // certain-keep flags
__device__ int   g_amb[NB * NPAT];            // ambiguous patch ids
__device__ float g_exc[NB * NPAT];            // exact scores of ambiguous
__device__ int   g_nA[NB], g_nC[NB];

// ---------------- helpers ----------------
static __device__ __forceinline__ uint cvt_bf2(float hi, float lo) {
    uint d;
    asm("cvt.rn.bf16x2.f32 %0, %1, %2;" : "=r"(d) : "f"(hi), "f"(lo));
    return d;
}
static __device__ __forceinline__ void mma16816(float* d, const uint* a,
                                                uint b0, uint b1) {
    asm("mma.sync.aligned.m16n8k16.row.col.f32.bf16.bf16.f32 "
        "{%0,%1,%2,%3}, {%4,%5,%6,%7}, {%8,%9}, {%0,%1,%2,%3};"
        : "+f"(d[0]), "+f"(d[1]), "+f"(d[2]), "+f"(d[3])
        : "r"(a[0]), "r"(a[1]), "r"(a[2]), "r"(a[3]), "r"(b0), "r"(b1));
}
static __device__ __forceinline__ void ffma2(ull& d, ull a, ull b) {
    asm("fma.rn.f32x2 %0, %1, %2, %0;" : "+l"(d) : "l"(a), "l"(b));
}
static __device__ __forceinline__ ull pack2(float v) {
    ull r;
    asm("mov.b64 %0, {%1, %1};" : "=l"(r) : "f"(v));
    return r;
}

// =====================================================================
// prep: W1 [256k x 64n] fp32 -> bf16 (hi) in m16n8k16 B-fragment order.
// =====================================================================
__global__ __launch_bounds__(256) void prep_W_kernel(const float* __restrict__ W1) {
    int u = blockIdx.x * 256 + threadIdx.x;     // 0..8191
    int reg = u & 1, lane = (u >> 1) & 31, ns = (u >> 6) & 7, ks = u >> 9;
    int g = lane >> 2, t = lane & 3;
    int k0 = ks * 16 + 2 * t + 8 * reg;
    int n  = ns * 8 + g;
    g_Wf[u] = cvt_bf2(W1[(k0 + 1) * HID + n], W1[k0 * HID + n]);
}

// =====================================================================
// approx scorer: one block = 128 tokens (1 image row). single-product
// bf16 HMMA GEMM (M=128, N=64, K=256) + fused epilogue.
// =====================================================================
__global__ __launch_bounds__(128, 4) void scorer_kernel(
    const float* __restrict__ tokens,
    const float* __restrict__ b1g,
    const float* __restrict__ W2g,
    const float* __restrict__ b2g)
{
    extern __shared__ char smem[];
    uint*  sA0  = (uint*)(smem + SM_A);
    float* sTok = (float*)(smem + SM_TOK);
    float* sb1  = (float*)(smem + SM_B1);
    float* sw2  = (float*)(smem + SM_W2);

    const int tid  = threadIdx.x;
    const int w    = tid >> 5;
    const int lane = tid & 31;
    const int blk  = blockIdx.x;

    if (tid < 64) { sb1[tid] = b1g[tid]; sw2[tid] = W2g[tid]; }

    float acc[2][8][4];
    #pragma unroll
    for (int a = 0; a < 2; a++)
        #pragma unroll
        for (int b = 0; b < 8; b++)
            #pragma unroll
            for (int c = 0; c < 4; c++) acc[a][b][c] = 0.f;

    const int m = tid;
    const int mstep = m >> 4, r = m & 15, q = r & 7, rh = r >> 3;
    const float4* rowp = (const float4*)(tokens + ((size_t)blk * 128 + m) * CDIM);
    const uint2* gWh = (const uint2*)g_Wf;

    for (int c = 0; c < 4; ++c) {               // 4 chunks of 64 channels
        uint* buf = sA0 + (c & 1) * A_WORDS;
        #pragma unroll
        for (int jj = 0; jj < 8; ++jj) {
            float4 a = rowp[c * 16 + 2 * jj];
            float4 b = rowp[c * 16 + 2 * jj + 1];
            uint h0 = cvt_bf2(a.y, a.x);
            uint h1 = cvt_bf2(a.w, a.z);
            uint h2 = cvt_bf2(b.y, b.x);
            uint h3 = cvt_bf2(b.w, b.z);
            int kl = jj >> 1, kh = jj & 1;
            uint w0 = (uint)((((kl * 8 + mstep) * 4) + rh + 2 * kh) * A_PAD + 4 * q);
            *(uint4*)(buf + w0) = make_uint4(h0, h1, h2, h3);   // STS.128
        }
        __syncthreads();

        #pragma unroll
        for (int kl = 0; kl < 4; ++kl) {
            uint Ah[2][4];
            #pragma unroll
            for (int dm = 0; dm < 2; ++dm) {
                int msel = 2 * w + dm;
                #pragma unroll
                for (int rg = 0; rg < 4; ++rg)
                    Ah[dm][rg] = buf[(uint)(((kl * 8 + msel) * 4 + rg) * A_PAD + lane)];
            }
            int ks = c * 4 + kl;
            #pragma unroll
            for (int ns = 0; ns < 8; ++ns) {
                uint2 bh = __ldg(&gWh[(uint)((ks * 8 + ns) * 32 + lane)]);
                mma16816(acc[0][ns], Ah[0], bh.x, bh.y);
                mma16816(acc[1][ns], Ah[1], bh.x, bh.y);
            }
        }
    }

    // epilogue: bias + relu + W2 dot, reduce k-lanes, sigmoid
    const int t4 = lane & 3, g = lane >> 2;
    const float b2v = b2g[0];
    float tv[4];
    #pragma unroll
    for (int dm = 0; dm < 2; ++dm)
        #pragma unroll
        for (int rh2 = 0; rh2 < 2; ++rh2) {
            float s = 0.f;
            #pragma unroll
            for (int ns = 0; ns < 8; ++ns)
                #pragma unroll
                for (int j = 0; j < 2; ++j) {
                    int n = ns * 8 + 2 * t4 + j;
                    float h = acc[dm][ns][2 * rh2 + j] + sb1[n];
                    s += fmaxf(h, 0.f) * sw2[n];
                }
            tv[dm * 2 + rh2] = s;
        }
    #pragma unroll
    for (int k = 0; k < 4; ++k) {
        tv[k] += __shfl_xor_sync(0xffffffffu, tv[k], 1);
        tv[k] += __shfl_xor_sync(0xffffffffu, tv[k], 2);
    }
    __syncthreads();
    if (t4 == 0) {
        #pragma unroll
        for (int k = 0; k < 4; ++k) {
            int dm = k >> 1, rh2 = k & 1;
            int token = (2 * w + dm) * 16 + g + 8 * rh2;
            sTok[token] = 1.f / (1.f + expf(-(tv[k] + b2v)));
        }
    }
    __syncthreads();

    if (tid < 16) {
        float sum = 0.f;
        #pragma unroll
        for (int cc = 0; cc < 8; ++cc) sum += sTok[tid * 8 + cc];
        int bb = blk >> 7, y = blk & 127;
        g_rowpart[(bb * HDIM + y) * 16 + tid] = sum;
    }
}

// =====================================================================
// select1: per batch. Approx ranking, find cut, classify into
// certain-keep / ambiguous (|s - cut| <= WINDOW) / certain-drop.
// =====================================================================
__global__ __launch_bounds__(256) void select1_kernel() {
    __shared__ float s[NPAT];
    __shared__ float sCut;
    __shared__ int flagA[NPAT];
    const int b = blockIdx.x;
    const int tid = threadIdx.x;
    const int ih = tid >> 4, iw = tid & 15;
    float sc = 0.f;
    #pragma unroll
    for (int r = 0; r < 8; r++)
        sc += g_rowpart[(b * HDIM + ih * 8 + r) * 16 + iw];
    s[tid] = sc;
    __syncthreads();
    float my = s[tid];
    int rank = 0;
    #pragma unroll 8
    for (int q = 0; q < NPAT; q++) {
        float v = s[q];
        rank += (v > my) || (v == my && q < tid);
    }
    if (rank == NKEEP - 1) sCut = my;
    __syncthreads();
    float d = my - sCut;
    int isC = (d > WINDOW) ? 1 : 0;
    int isA = (fabsf(d) <= WINDOW) ? 1 : 0;
    flagA[tid] = isA;
    g_keepC[b * NPAT + tid] = isC;
    __syncthreads();
    if (isA) {
        int pos = 0;
        for (int q = 0; q < tid; q++) pos += flagA[q];
        g_amb[b * NPAT + pos] = tid;
    }
    if (tid == 0) {
        int nA = 0;
        for (int q = 0; q < NPAT; q++) nA += flagA[q];
        g_nA[b] = nA;
    }
    if (tid == 1) {
        int nC = 0;
        for (int q = 0; q < NPAT; q++)
            nC += (int)(s[q] - sCut > WINDOW);
        g_nC[b] = nC;
    }
}

// =====================================================================
// rescore: exact fp32 score for ambiguous patches (nA ~ 2/batch).
// One block per ambiguous patch (grid (RSX, NB), early exit).
// W1 AND the patch's 64 tokens are staged into smem with parallel
// LDG.128 (latency amortized); compute is pure-LDS FFMA2.
// =====================================================================
__global__ __launch_bounds__(256) void rescore_kernel(
    const float* __restrict__ tokens,
    const float* __restrict__ W1,
    const float* __restrict__ b1,
    const float* __restrict__ W2,
    const float* __restrict__ b2)
{
    const int b = blockIdx.y;
    const int nA = g_nA[b];
    if (blockIdx.x >= nA) return;               // uniform across block

    extern __shared__ char rsm[];
    float* sW = (float*)rsm;                    // [256][64]  = 64 KB
    float* sX = sW + CDIM * HID;                // [64][256]  = 64 KB
    float* sp = sX + 64 * CDIM;                 // 256 f
    float* st = sp + 256;                       // 64 f

    const int tid = threadIdx.x;

    // ---- stage W1 once (256 thr x 16 LDG.128, huge MLP) ----
    {
        const float4* src = (const float4*)W1;
        float4* dst = (float4*)sW;
        #pragma unroll
        for (int i = 0; i < 16; i++)
            dst[i * 256 + tid] = __ldg(&src[i * 256 + tid]);
    }

    const int t  = tid >> 2, hh = tid & 3;      // token 0..63, hidden group
    const int hb = hh * 16;
    const int rowq = tid & 3;                   // token-row quarter staged

    for (int j = blockIdx.x; j < nA; j += RSX) {
        const int p = g_amb[b * NPAT + j];
        const int ih = p >> 4, iw = p & 15;

        // ---- stage this patch's 64 token rows (64 KB) ----
        {
            const int tt = tid >> 2;            // token staged by this thread
            const int tr = tt >> 3, tc = tt & 7;
            const int tokIdx = b * NTOK + (ih * 8 + tr) * WDIM + iw * 8 + tc;
            const float4* src = (const float4*)(tokens + (size_t)tokIdx * CDIM);
            float4* dst = (float4*)(sX + tt * CDIM);
            #pragma unroll
            for (int i = 0; i < 16; i++)
                dst[rowq * 16 + i] = __ldg(&src[rowq * 16 + i]);
        }
        __syncthreads();

        ull hacc[8];                            // 16 hidden as 8 f32 pairs
        const ull* b1p = (const ull*)(b1 + hb);
        #pragma unroll
        for (int i = 0; i < 8; i++) hacc[i] = __ldg(&b1p[i]);

        const float4* xrow = (const float4*)(sX + t * CDIM);
        #pragma unroll 4
        for (int c4 = 0; c4 < 64; ++c4) {
            float4 xv = xrow[c4];               // LDS.128, broadcast x4 lanes
            #pragma unroll
            for (int rr4 = 0; rr4 < 4; ++rr4) {
                float xc = (rr4 == 0) ? xv.x : (rr4 == 1) ? xv.y
                         : (rr4 == 2) ? xv.z : xv.w;
                ull xp = pack2(xc);
                const ulonglong2* wp =
                    (const ulonglong2*)(sW + (c4 * 4 + rr4) * HID + hb);
                ulonglong2 wA = wp[0];
                ulonglong2 wB = wp[1];
                ulonglong2 wC = wp[2];
                ulonglong2 wD = wp[3];
                ffma2(hacc[0], xp, wA.x); ffma2(hacc[1], xp, wA.y);
                ffma2(hacc[2], xp, wB.x); ffma2(hacc[3], xp, wB.y);
                ffma2(hacc[4], xp, wC.x); ffma2(hacc[5], xp, wC.y);
                ffma2(hacc[6], xp, wD.x); ffma2(hacc[7], xp, wD.y);
            }
        }
        float z = 0.f;
        #pragma unroll
        for (int i = 0; i < 8; i++) {
            float lo = __uint_as_float((uint)hacc[i]);
            float hi = __uint_as_float((uint)(hacc[i] >> 32));
            z += fmaxf(lo, 0.f) * __ldg(&W2[hb + 2 * i])
               + fmaxf(hi, 0.f) * __ldg(&W2[hb + 2 * i + 1]);
        }
        sp[t * 4 + hh] = z;
        __syncthreads();
        if (tid < 64) {
            float zz = b2[0] + sp[tid * 4] + sp[tid * 4 + 1]
                     + sp[tid * 4 + 2] + sp[tid * 4 + 3];
            st[tid] = 1.f / (1.f + expf(-zz));
        }
        __syncthreads();
        if (tid == 0) {
            float sum = 0.f;
            for (int q = 0; q < 64; q++) sum += st[q];
            g_exc[b * NPAT + j] = sum * (1.f / 64.f);
        }
        __syncthreads();
    }
}

// =====================================================================
// select2: merge certain keeps + top-(NKEEP - nC) ambiguous by exact
// score (desc, index asc). Emit kept ids ascending, pad -1.
// =====================================================================
__global__ __launch_bounds__(256) void select2_kernel() {
    __shared__ int keepF[NPAT];
    __shared__ float e[NPAT];
    __shared__ int aid[NPAT];
    const int b = blockIdx.x;
    const int tid = threadIdx.x;
    const int nA = g_nA[b];
    const int slots = NKEEP - g_nC[b];
    keepF[tid] = g_keepC[b * NPAT + tid];
    if (tid < nA) {
        e[tid] = g_exc[b * NPAT + tid];
        aid[tid] = g_amb[b * NPAT + tid];
    }
    __syncthreads();
    if (tid < nA) {
        float my = e[tid];
        int rank = 0;
        for (int q = 0; q < nA; q++) {
            float v = e[q];
            rank += (v > my) || (v == my && q < tid);
        }
        if (rank < slots) keepF[aid[tid]] = 1;
    }
    __syncthreads();
    int kept = keepF[tid];
    if (kept) {
        int pos = 0;
        for (int q = 0; q < tid; q++) pos += keepF[q];
        g_kept[b * NPOUT + pos] = tid;
    }
    if (tid >= NKEEP && tid < NPOUT) g_kept[b * NPOUT + tid] = -1;
}

// =====================================================================
// gather: one block per output patch slot. Streaming stores.
// =====================================================================
__global__ __launch_bounds__(256) void gather_kernel(
    const float4* __restrict__ tokens, float4* __restrict__ out)
{
    const int bk = blockIdx.x;
    const int b  = bk / NPOUT;
    const int kp = bk % NPOUT;
    const int s  = g_kept[b * NPOUT + kp];
    const int kh = kp >> 4, kw = kp & 15;

    const float4* srcB = tokens + (size_t)b * (NTOK * C4);
    float4* dstB = out + (size_t)b * (OUT_TOK * C4);

    int sih = 0, siw = 0;
    if (s >= 0) { sih = s >> 4; siw = s & 15; }
    const float4 zero = make_float4(0.f, 0.f, 0.f, 0.f);

    #pragma unroll
    for (int i = 0; i < 16; i++) {
        int idx = i * 256 + threadIdx.x;
        int tp  = idx >> 6;
        int c4  = idx & 63;
        int ph = tp >> 3, pw = tp & 7;
        int dstTok = (kh * 8 + ph) * WDIM + kw * 8 + pw;
        float4 v = zero;
        if (s >= 0) {
            int srcTok = (sih * 8 + ph) * WDIM + siw * 8 + pw;
            v = __ldg(&srcB[srcTok * C4 + c4]);
        }
        __stcs(&dstB[dstTok * C4 + c4], v);
    }
}

// =====================================================================
extern "C" void kernel_launch(void* const* d_in, const int* in_sizes, int n_in,
                              void* d_out, int out_size)
{
    const float* tokens = (const float*)d_in[0];
    const float* W1 = (const float*)d_in[1];
    const float* b1 = (const float*)d_in[2];
    const float* W2 = (const float*)d_in[3];
    const float* b2 = (const float*)d_in[4];
    float* out = (float*)d_out;

    cudaFuncSetAttribute(scorer_kernel,
                         cudaFuncAttributeMaxDynamicSharedMemorySize, SMEM_BYTES);
    cudaFuncSetAttribute(rescore_kernel,
                         cudaFuncAttributeMaxDynamicSharedMemorySize, RS_SMEM_BYTES);

    prep_W_kernel<<<32, 256>>>(W1);
    scorer_kernel<<<NB * HDIM, 128, SMEM_BYTES>>>(tokens, b1, W2, b2);
    select1_kernel<<<NB, 256>>>();
    rescore_kernel<<<dim3(RSX, NB), 256, RS_SMEM_BYTES>>>(tokens, W1, b1, W2, b2);
    select2_kernel<<<NB, 256>>>();
    gather_kernel<<<NB * NPOUT, 256>>>((const float4*)tokens, (float4*)out);
}